// round 2
// baseline (speedup 1.0000x reference)
#include <cuda_runtime.h>
#include <cstdint>

#define DN 128          // embedding dim
#define MAXN 200002     // USERS + ITEMS

// Ping-pong scratch for layer activations (no allocation allowed -> static device arrays)
__device__ float g_bufA[(size_t)MAXN * DN];
__device__ float g_bufB[(size_t)MAXN * DN];

// ---------------------------------------------------------------------------
// init: acc (d_out) = emb, bufA = emb, bufB = 0     (vectorized float4)
// ---------------------------------------------------------------------------
__global__ void init_kernel(const float4* __restrict__ emb,
                            float4* __restrict__ acc,
                            float4* __restrict__ xa,
                            float4* __restrict__ xb,
                            int total4) {
    int i = blockIdx.x * blockDim.x + threadIdx.x;
    if (i >= total4) return;
    float4 e = emb[i];
    acc[i] = e;
    xa[i] = e;
    xb[i] = make_float4(0.f, 0.f, 0.f, 0.f);
}

// ---------------------------------------------------------------------------
// spmm: y[row] += val * x[col], warp per edge, red.global.add.v4.f32 scatter
// ---------------------------------------------------------------------------
__global__ void __launch_bounds__(256) spmm_kernel(
        const float* __restrict__ x,
        float* __restrict__ y,
        const float* __restrict__ vals,
        const int* __restrict__ rows,
        const int* __restrict__ cols,
        int nnz) {
    int warp = (blockIdx.x * blockDim.x + threadIdx.x) >> 5;
    int lane = threadIdx.x & 31;
    if (warp >= nnz) return;

    int r = __ldg(rows + warp);
    int c = __ldg(cols + warp);
    float v = __ldg(vals + warp);

    const float4* xrow = reinterpret_cast<const float4*>(x + (size_t)c * DN);
    float4 m = __ldg(xrow + lane);

    float* yp = y + (size_t)r * DN + lane * 4;
    float a = m.x * v, b = m.y * v, cc = m.z * v, d = m.w * v;
    asm volatile("red.global.add.v4.f32 [%0], {%1, %2, %3, %4};"
                 :: "l"(yp), "f"(a), "f"(b), "f"(cc), "f"(d)
                 : "memory");
}

// ---------------------------------------------------------------------------
// accumulate layer result into acc and zero the next spmm target in one pass
// ---------------------------------------------------------------------------
__global__ void acc_zero_kernel(float4* __restrict__ acc,
                                const float4* __restrict__ y,
                                float4* __restrict__ next_target,
                                int total4) {
    int i = blockIdx.x * blockDim.x + threadIdx.x;
    if (i >= total4) return;
    float4 a = acc[i];
    float4 yy = y[i];
    a.x += yy.x; a.y += yy.y; a.z += yy.z; a.w += yy.w;
    acc[i] = a;
    next_target[i] = make_float4(0.f, 0.f, 0.f, 0.f);
}

// ---------------------------------------------------------------------------
// final: acc = (acc + y) * 0.25
// ---------------------------------------------------------------------------
__global__ void final_kernel(float4* __restrict__ acc,
                             const float4* __restrict__ y,
                             int total4) {
    int i = blockIdx.x * blockDim.x + threadIdx.x;
    if (i >= total4) return;
    float4 a = acc[i];
    float4 yy = y[i];
    a.x = (a.x + yy.x) * 0.25f;
    a.y = (a.y + yy.y) * 0.25f;
    a.z = (a.z + yy.z) * 0.25f;
    a.w = (a.w + yy.w) * 0.25f;
    acc[i] = a;
}

// ---------------------------------------------------------------------------
// Inputs (metadata order): emb [N*D] f32, edge_vals [nnz] f32,
//                          edge_row [nnz] i32, edge_col [nnz] i32
// Output: mean matrix [N*D] f32
// ---------------------------------------------------------------------------
extern "C" void kernel_launch(void* const* d_in, const int* in_sizes, int n_in,
                              void* d_out, int out_size) {
    const float* emb  = (const float*)d_in[0];
    const float* vals = (const float*)d_in[1];
    const int*   rows = (const int*)d_in[2];
    const int*   cols = (const int*)d_in[3];
    float* acc = (float*)d_out;

    int nnz    = in_sizes[1];
    int totalF = in_sizes[0];          // N * D
    int total4 = totalF / 4;

    float* bufA;
    float* bufB;
    cudaGetSymbolAddress((void**)&bufA, g_bufA);
    cudaGetSymbolAddress((void**)&bufB, g_bufB);

    const int TB = 256;
    int ew_blocks   = (total4 + TB - 1) / TB;
    int spmm_blocks = (int)(((long long)nnz * 32 + TB - 1) / TB);

    // acc = emb, x(A) = emb, y(B) = 0
    init_kernel<<<ew_blocks, TB>>>((const float4*)emb, (float4*)acc,
                                   (float4*)bufA, (float4*)bufB, total4);

    // layer 1: B = A_norm @ A ;  acc += B ; zero A
    spmm_kernel<<<spmm_blocks, TB>>>(bufA, bufB, vals, rows, cols, nnz);
    acc_zero_kernel<<<ew_blocks, TB>>>((float4*)acc, (const float4*)bufB,
                                       (float4*)bufA, total4);

    // layer 2: A = A_norm @ B ;  acc += A ; zero B
    spmm_kernel<<<spmm_blocks, TB>>>(bufB, bufA, vals, rows, cols, nnz);
    acc_zero_kernel<<<ew_blocks, TB>>>((float4*)acc, (const float4*)bufA,
                                       (float4*)bufB, total4);

    // layer 3: B = A_norm @ A ;  acc = (acc + B) / 4
    spmm_kernel<<<spmm_blocks, TB>>>(bufA, bufB, vals, rows, cols, nnz);
    final_kernel<<<ew_blocks, TB>>>((float4*)acc, (const float4*)bufB, total4);
}

// round 3
// speedup vs baseline: 2.4276x; 2.4276x over previous
#include <cuda_runtime.h>
#include <cstdint>

#define DN 128              // embedding dim
#define DV 32               // DN/4 float4 per row
#define MAXN 200002         // USERS + ITEMS
#define MAXNNZ 2000000      // 2 * E

#define SCAN_BLK 256
#define SCAN_IPT 16
#define SCAN_CHUNK (SCAN_BLK * SCAN_IPT)   // 4096
#define MAX_SCAN_BLOCKS 64                 // ceil(200002/4096) = 49

// ---- static device scratch (no allocation allowed) ----
__device__ float g_bufA[(size_t)MAXN * DN];   // x1
__device__ float g_bufB[(size_t)MAXN * DN];   // x2
__device__ int   g_deg[MAXN];
__device__ int   g_rowptr[MAXN];
__device__ int   g_cursor[MAXN];
__device__ int   g_bsum[MAX_SCAN_BLOCKS];
__device__ int2  g_edge[MAXNNZ];              // packed (col, float_as_int(val)) sorted by row

// ---------------------------------------------------------------------------
// CSR build
// ---------------------------------------------------------------------------
__global__ void zero_deg_kernel(int n) {
    int i = blockIdx.x * blockDim.x + threadIdx.x;
    if (i < n) g_deg[i] = 0;
}

__global__ void hist_kernel(const int* __restrict__ rows, int nnz) {
    int e = blockIdx.x * blockDim.x + threadIdx.x;
    if (e < nnz) atomicAdd(&g_deg[rows[e]], 1);
}

__global__ void scan_reduce_kernel(int n) {
    __shared__ int s[SCAN_BLK];
    int base = blockIdx.x * SCAN_CHUNK + threadIdx.x * SCAN_IPT;
    int sum = 0;
#pragma unroll
    for (int i = 0; i < SCAN_IPT; i++) {
        int idx = base + i;
        if (idx < n) sum += g_deg[idx];
    }
    s[threadIdx.x] = sum;
    __syncthreads();
    for (int off = SCAN_BLK / 2; off > 0; off >>= 1) {
        if (threadIdx.x < off) s[threadIdx.x] += s[threadIdx.x + off];
        __syncthreads();
    }
    if (threadIdx.x == 0) g_bsum[blockIdx.x] = s[0];
}

__global__ void scan_top_kernel(int nb) {
    // single thread exclusive scan over <=64 block sums
    int acc = 0;
    for (int i = 0; i < nb; i++) {
        int v = g_bsum[i];
        g_bsum[i] = acc;
        acc += v;
    }
}

__global__ void scan_down_kernel(int n) {
    int tid = threadIdx.x;
    int base = blockIdx.x * SCAN_CHUNK + tid * SCAN_IPT;
    int local[SCAN_IPT];
    int sum = 0;
#pragma unroll
    for (int i = 0; i < SCAN_IPT; i++) {
        int idx = base + i;
        int v = (idx < n) ? g_deg[idx] : 0;
        local[i] = sum;       // exclusive within thread
        sum += v;
    }
    // block exclusive scan of per-thread sums
    int lane = tid & 31, wid = tid >> 5;
    int v = sum;
#pragma unroll
    for (int o = 1; o < 32; o <<= 1) {
        int t = __shfl_up_sync(0xFFFFFFFFu, v, o);
        if (lane >= o) v += t;
    }
    __shared__ int wsum[SCAN_BLK / 32];
    if (lane == 31) wsum[wid] = v;
    __syncthreads();
    if (tid < SCAN_BLK / 32) {
        int w = wsum[tid];
#pragma unroll
        for (int o = 1; o < SCAN_BLK / 32; o <<= 1) {
            int t = __shfl_up_sync(0xFFu, w, o);
            if (tid >= o) w += t;
        }
        wsum[tid] = w;
    }
    __syncthreads();
    int thread_excl = v - sum + (wid ? wsum[wid - 1] : 0);
    int off = thread_excl + g_bsum[blockIdx.x];
#pragma unroll
    for (int i = 0; i < SCAN_IPT; i++) {
        int idx = base + i;
        if (idx < n) {
            int p = off + local[i];
            g_rowptr[idx] = p;
            g_cursor[idx] = p;
        }
    }
}

__global__ void scatter_kernel(const int* __restrict__ rows,
                               const int* __restrict__ cols,
                               const float* __restrict__ vals,
                               int nnz) {
    int e = blockIdx.x * blockDim.x + threadIdx.x;
    if (e >= nnz) return;
    int r = rows[e];
    int pos = atomicAdd(&g_cursor[r], 1);
    g_edge[pos] = make_int2(cols[e], __float_as_int(vals[e]));
}

// ---------------------------------------------------------------------------
// pull SpMM: warp per row, y[r] = sum_e val_e * x[col_e]
// FUSE: y[r] = (sum + emb[r] + x1[r] + x2[r]) * 0.25
// ---------------------------------------------------------------------------
template <bool FUSE>
__global__ void __launch_bounds__(256) spmm_pull_kernel(
        const float4* __restrict__ x,
        float4* __restrict__ y,
        const float4* __restrict__ emb,
        const float4* __restrict__ x1,
        const float4* __restrict__ x2,
        int n) {
    int w = (blockIdx.x * blockDim.x + threadIdx.x) >> 5;
    int lane = threadIdx.x & 31;
    if (w >= n) return;

    int start = g_rowptr[w];
    int end = start + g_deg[w];

    float4 a0 = make_float4(0.f, 0.f, 0.f, 0.f);
    float4 a1 = make_float4(0.f, 0.f, 0.f, 0.f);

    int e = start;
    for (; e + 2 <= end; e += 2) {
        int2 e0 = g_edge[e];
        int2 e1 = g_edge[e + 1];
        float v0 = __int_as_float(e0.y);
        float v1 = __int_as_float(e1.y);
        float4 m0 = __ldg(x + (size_t)e0.x * DV + lane);
        float4 m1 = __ldg(x + (size_t)e1.x * DV + lane);
        a0.x += v0 * m0.x; a0.y += v0 * m0.y; a0.z += v0 * m0.z; a0.w += v0 * m0.w;
        a1.x += v1 * m1.x; a1.y += v1 * m1.y; a1.z += v1 * m1.z; a1.w += v1 * m1.w;
    }
    if (e < end) {
        int2 e0 = g_edge[e];
        float v0 = __int_as_float(e0.y);
        float4 m0 = __ldg(x + (size_t)e0.x * DV + lane);
        a0.x += v0 * m0.x; a0.y += v0 * m0.y; a0.z += v0 * m0.z; a0.w += v0 * m0.w;
    }

    float4 r;
    r.x = a0.x + a1.x; r.y = a0.y + a1.y; r.z = a0.z + a1.z; r.w = a0.w + a1.w;

    size_t oidx = (size_t)w * DV + lane;
    if (FUSE) {
        float4 eb = __ldg(emb + oidx);
        float4 b1 = __ldg(x1 + oidx);
        float4 b2 = __ldg(x2 + oidx);
        r.x = (r.x + eb.x + b1.x + b2.x) * 0.25f;
        r.y = (r.y + eb.y + b1.y + b2.y) * 0.25f;
        r.z = (r.z + eb.z + b1.z + b2.z) * 0.25f;
        r.w = (r.w + eb.w + b1.w + b2.w) * 0.25f;
    }
    y[oidx] = r;
}

// ---------------------------------------------------------------------------
// Inputs: emb [N*D] f32, edge_vals [nnz] f32, edge_row [nnz] i32, edge_col [nnz] i32
// Output: mean matrix [N*D] f32
// ---------------------------------------------------------------------------
extern "C" void kernel_launch(void* const* d_in, const int* in_sizes, int n_in,
                              void* d_out, int out_size) {
    const float* emb  = (const float*)d_in[0];
    const float* vals = (const float*)d_in[1];
    const int*   rows = (const int*)d_in[2];
    const int*   cols = (const int*)d_in[3];
    float* out = (float*)d_out;

    int nnz = in_sizes[1];
    int n   = in_sizes[0] / DN;        // number of rows (USERS + ITEMS)

    float* bufA;
    float* bufB;
    cudaGetSymbolAddress((void**)&bufA, g_bufA);
    cudaGetSymbolAddress((void**)&bufB, g_bufB);

    const int TB = 256;
    int nb_scan   = (n + SCAN_CHUNK - 1) / SCAN_CHUNK;
    int deg_blocks  = (n + TB - 1) / TB;
    int edge_blocks = (nnz + TB - 1) / TB;
    int spmm_blocks = (n * 32 + TB - 1) / TB;

    // --- CSR build (same edges every call; rebuilt deterministically) ---
    zero_deg_kernel<<<deg_blocks, TB>>>(n);
    hist_kernel<<<edge_blocks, TB>>>(rows, nnz);
    scan_reduce_kernel<<<nb_scan, SCAN_BLK>>>(n);
    scan_top_kernel<<<1, 1>>>(nb_scan);
    scan_down_kernel<<<nb_scan, SCAN_BLK>>>(n);
    scatter_kernel<<<edge_blocks, TB>>>(rows, cols, vals, nnz);

    // --- 3 propagation layers, pull-based ---
    // x1 = A @ emb
    spmm_pull_kernel<false><<<spmm_blocks, TB>>>(
        (const float4*)emb, (float4*)bufA, nullptr, nullptr, nullptr, n);
    // x2 = A @ x1
    spmm_pull_kernel<false><<<spmm_blocks, TB>>>(
        (const float4*)bufA, (float4*)bufB, nullptr, nullptr, nullptr, n);
    // out = (A @ x2 + emb + x1 + x2) * 0.25
    spmm_pull_kernel<true><<<spmm_blocks, TB>>>(
        (const float4*)bufB, (float4*)out,
        (const float4*)emb, (const float4*)bufA, (const float4*)bufB, n);
}

// round 5
// speedup vs baseline: 2.6279x; 1.0825x over previous
#include <cuda_runtime.h>
#include <cuda_fp16.h>
#include <cstdint>

#define DN 128              // embedding dim
#define MAXN 200002         // USERS + ITEMS
#define MAXNNZ 2000000      // 2 * E

#define SCAN_BLK 256
#define SCAN_IPT 16
#define SCAN_CHUNK (SCAN_BLK * SCAN_IPT)   // 4096
#define MAX_SCAN_BLOCKS 64                 // ceil(200002/4096) = 49

// ---- static device scratch (no allocation allowed) ----
// half activations: 200002*128*2B = 51.2 MB each
__device__ __half g_xe[(size_t)MAXN * DN];    // emb in fp16
__device__ __half g_x1[(size_t)MAXN * DN];    // layer-1 out (fp16)
__device__ __half g_x2[(size_t)MAXN * DN];    // layer-2 out (fp16)
__device__ int   g_deg[MAXN];
__device__ int   g_rowptr[MAXN];
__device__ int   g_cursor[MAXN];
__device__ int   g_bsum[MAX_SCAN_BLOCKS];
__device__ int2  g_edge[MAXNNZ];              // (col, float_bits(val)) grouped by row

// ---------------------------------------------------------------------------
// CSR build
// ---------------------------------------------------------------------------
__global__ void zero_deg_kernel(int n) {
    int i = blockIdx.x * blockDim.x + threadIdx.x;
    if (i < n) g_deg[i] = 0;
}

__global__ void hist_kernel(const int* __restrict__ rows, int nnz) {
    int e = blockIdx.x * blockDim.x + threadIdx.x;
    if (e < nnz) atomicAdd(&g_deg[rows[e]], 1);
}

__global__ void scan_reduce_kernel(int n) {
    __shared__ int s[SCAN_BLK];
    int base = blockIdx.x * SCAN_CHUNK + threadIdx.x * SCAN_IPT;
    int sum = 0;
#pragma unroll
    for (int i = 0; i < SCAN_IPT; i++) {
        int idx = base + i;
        if (idx < n) sum += g_deg[idx];
    }
    s[threadIdx.x] = sum;
    __syncthreads();
    for (int off = SCAN_BLK / 2; off > 0; off >>= 1) {
        if (threadIdx.x < off) s[threadIdx.x] += s[threadIdx.x + off];
        __syncthreads();
    }
    if (threadIdx.x == 0) g_bsum[blockIdx.x] = s[0];
}

// 64-thread block exclusive scan over the <=64 block sums (was serial before)
__global__ void scan_top_kernel(int nb) {
    __shared__ int s[64];
    int t = threadIdx.x;
    int own = (t < nb) ? g_bsum[t] : 0;
    s[t] = own;
    __syncthreads();
#pragma unroll
    for (int o = 1; o < 64; o <<= 1) {
        int v = (t >= o) ? s[t - o] : 0;
        __syncthreads();
        s[t] += v;
        __syncthreads();
    }
    if (t < nb) g_bsum[t] = s[t] - own;   // exclusive
}

__global__ void scan_down_kernel(int n) {
    int tid = threadIdx.x;
    int base = blockIdx.x * SCAN_CHUNK + tid * SCAN_IPT;
    int local[SCAN_IPT];
    int sum = 0;
#pragma unroll
    for (int i = 0; i < SCAN_IPT; i++) {
        int idx = base + i;
        int v = (idx < n) ? g_deg[idx] : 0;
        local[i] = sum;
        sum += v;
    }
    int lane = tid & 31, wid = tid >> 5;
    int v = sum;
#pragma unroll
    for (int o = 1; o < 32; o <<= 1) {
        int t = __shfl_up_sync(0xFFFFFFFFu, v, o);
        if (lane >= o) v += t;
    }
    __shared__ int wsum[SCAN_BLK / 32];
    if (lane == 31) wsum[wid] = v;
    __syncthreads();
    if (tid < SCAN_BLK / 32) {
        int w = wsum[tid];
#pragma unroll
        for (int o = 1; o < SCAN_BLK / 32; o <<= 1) {
            int t = __shfl_up_sync(0xFFu, w, o);
            if (tid >= o) w += t;
        }
        wsum[tid] = w;
    }
    __syncthreads();
    int thread_excl = v - sum + (wid ? wsum[wid - 1] : 0);
    int off = thread_excl + g_bsum[blockIdx.x];
#pragma unroll
    for (int i = 0; i < SCAN_IPT; i++) {
        int idx = base + i;
        if (idx < n) {
            int p = off + local[i];
            g_rowptr[idx] = p;
            g_cursor[idx] = p;
        }
    }
}

__global__ void scatter_kernel(const int* __restrict__ rows,
                               const int* __restrict__ cols,
                               const float* __restrict__ vals,
                               int nnz) {
    int e = blockIdx.x * blockDim.x + threadIdx.x;
    if (e >= nnz) return;
    int r = rows[e];
    int pos = atomicAdd(&g_cursor[r], 1);
    g_edge[pos] = make_int2(cols[e], __float_as_int(vals[e]));
}

// ---------------------------------------------------------------------------
// emb (f32) -> f16
// ---------------------------------------------------------------------------
__global__ void f2h_kernel(const float4* __restrict__ src,
                           uint2* __restrict__ dst, int total4) {
    int i = blockIdx.x * blockDim.x + threadIdx.x;
    if (i >= total4) return;
    float4 v = src[i];
    __half2 a = __float22half2_rn(make_float2(v.x, v.y));
    __half2 b = __float22half2_rn(make_float2(v.z, v.w));
    uint2 r;
    r.x = *reinterpret_cast<unsigned int*>(&a);
    r.y = *reinterpret_cast<unsigned int*>(&b);
    dst[i] = r;
}

// ---------------------------------------------------------------------------
// pull SpMM, fp16 operand, fp32 accumulation. Warp per row, lane owns 4 dims
// (one uint2 = 4 halves per lane; 32 lanes * 8B = 256B row).
// FUSE epilogue: out(f32) = (sum + emb + x1 + x2) * 0.25
// ---------------------------------------------------------------------------
__device__ __forceinline__ float2 h2f_lo(unsigned u) {
    __half2 h = *reinterpret_cast<__half2*>(&u);
    return __half22float2(h);
}

template <bool FUSE>
__global__ void __launch_bounds__(256) spmm_half_kernel(
        const uint2* __restrict__ x,          // fp16 activations, gathered
        uint2* __restrict__ yh,               // fp16 out (non-fused layers)
        const float4* __restrict__ emb,       // fp32 (fused layer only)
        const uint2* __restrict__ x1,         // fp16 (fused layer only)
        const uint2* __restrict__ x2,         // fp16 (fused layer only)
        float4* __restrict__ outf,            // fp32 out (fused layer only)
        int n) {
    int w = (blockIdx.x * blockDim.x + threadIdx.x) >> 5;
    int lane = threadIdx.x & 31;
    if (w >= n) return;

    int start = g_rowptr[w];
    int end = start + g_deg[w];

    float a0x = 0.f, a0y = 0.f, a0z = 0.f, a0w = 0.f;
    float a1x = 0.f, a1y = 0.f, a1z = 0.f, a1w = 0.f;

    int e = start;
    for (; e + 2 <= end; e += 2) {
        int2 e0 = g_edge[e];
        int2 e1 = g_edge[e + 1];
        float v0 = __int_as_float(e0.y);
        float v1 = __int_as_float(e1.y);
        uint2 m0 = __ldg(x + (size_t)e0.x * 32 + lane);
        uint2 m1 = __ldg(x + (size_t)e1.x * 32 + lane);
        float2 f00 = h2f_lo(m0.x), f01 = h2f_lo(m0.y);
        float2 f10 = h2f_lo(m1.x), f11 = h2f_lo(m1.y);
        a0x += v0 * f00.x; a0y += v0 * f00.y; a0z += v0 * f01.x; a0w += v0 * f01.y;
        a1x += v1 * f10.x; a1y += v1 * f10.y; a1z += v1 * f11.x; a1w += v1 * f11.y;
    }
    if (e < end) {
        int2 e0 = g_edge[e];
        float v0 = __int_as_float(e0.y);
        uint2 m0 = __ldg(x + (size_t)e0.x * 32 + lane);
        float2 f00 = h2f_lo(m0.x), f01 = h2f_lo(m0.y);
        a0x += v0 * f00.x; a0y += v0 * f00.y; a0z += v0 * f01.x; a0w += v0 * f01.y;
    }

    float rx = a0x + a1x, ry = a0y + a1y, rz = a0z + a1z, rw = a0w + a1w;

    size_t oidx = (size_t)w * 32 + lane;
    if (FUSE) {
        float4 eb = __ldg(emb + oidx);
        uint2 u1 = __ldg(x1 + oidx);
        uint2 u2 = __ldg(x2 + oidx);
        float2 b10 = h2f_lo(u1.x), b11 = h2f_lo(u1.y);
        float2 b20 = h2f_lo(u2.x), b21 = h2f_lo(u2.y);
        float4 o;
        o.x = (rx + eb.x + b10.x + b20.x) * 0.25f;
        o.y = (ry + eb.y + b10.y + b20.y) * 0.25f;
        o.z = (rz + eb.z + b11.x + b21.x) * 0.25f;
        o.w = (rw + eb.w + b11.y + b21.y) * 0.25f;
        outf[oidx] = o;
    } else {
        __half2 ha = __float22half2_rn(make_float2(rx, ry));
        __half2 hb = __float22half2_rn(make_float2(rz, rw));
        uint2 r;
        r.x = *reinterpret_cast<unsigned int*>(&ha);
        r.y = *reinterpret_cast<unsigned int*>(&hb);
        yh[oidx] = r;
    }
}

// ---------------------------------------------------------------------------
// Inputs: emb [N*D] f32, edge_vals [nnz] f32, edge_row [nnz] i32, edge_col [nnz] i32
// Output: mean matrix [N*D] f32
// ---------------------------------------------------------------------------
extern "C" void kernel_launch(void* const* d_in, const int* in_sizes, int n_in,
                              void* d_out, int out_size) {
    const float* emb  = (const float*)d_in[0];
    const float* vals = (const float*)d_in[1];
    const int*   rows = (const int*)d_in[2];
    const int*   cols = (const int*)d_in[3];
    float* out = (float*)d_out;

    int nnz = in_sizes[1];
    int n   = in_sizes[0] / DN;

    __half* xe; __half* x1; __half* x2;
    cudaGetSymbolAddress((void**)&xe, g_xe);
    cudaGetSymbolAddress((void**)&x1, g_x1);
    cudaGetSymbolAddress((void**)&x2, g_x2);

    const int TB = 256;
    int total4 = in_sizes[0] / 4;
    int nb_scan     = (n + SCAN_CHUNK - 1) / SCAN_CHUNK;
    int deg_blocks  = (n + TB - 1) / TB;
    int edge_blocks = (nnz + TB - 1) / TB;
    int ew_blocks   = (total4 + TB - 1) / TB;
    int spmm_blocks = (n * 32 + TB - 1) / TB;

    // --- CSR build ---
    zero_deg_kernel<<<deg_blocks, TB>>>(n);
    hist_kernel<<<edge_blocks, TB>>>(rows, nnz);
    scan_reduce_kernel<<<nb_scan, SCAN_BLK>>>(n);
    scan_top_kernel<<<1, 64>>>(nb_scan);
    scan_down_kernel<<<nb_scan, SCAN_BLK>>>(n);
    scatter_kernel<<<edge_blocks, TB>>>(rows, cols, vals, nnz);

    // --- emb -> fp16 ---
    f2h_kernel<<<ew_blocks, TB>>>((const float4*)emb, (uint2*)xe, total4);

    // --- 3 layers, fp16 operands / fp32 accumulate ---
    // x1 = A @ emb
    spmm_half_kernel<false><<<spmm_blocks, TB>>>(
        (const uint2*)xe, (uint2*)x1, nullptr, nullptr, nullptr, nullptr, n);
    // x2 = A @ x1
    spmm_half_kernel<false><<<spmm_blocks, TB>>>(
        (const uint2*)x1, (uint2*)x2, nullptr, nullptr, nullptr, nullptr, n);
    // out = (A @ x2 + emb + x1 + x2) * 0.25   (fp32 out)
    spmm_half_kernel<true><<<spmm_blocks, TB>>>(
        (const uint2*)x2, nullptr,
        (const float4*)emb, (const uint2*)x1, (const uint2*)x2,
        (float4*)out, n);
}

// round 8
// speedup vs baseline: 3.2909x; 1.2523x over previous
#include <cuda_runtime.h>
#include <cuda_fp16.h>
#include <cstdint>

#define DN 128              // embedding dim
#define MAXN 200002         // USERS + ITEMS
#define MAXNNZ 2000000      // 2 * E

#define SCAN_BLK 256
#define SCAN_IPT 16
#define SCAN_CHUNK (SCAN_BLK * SCAN_IPT)   // 4096
#define MAX_SCAN_BLOCKS 64

// ---- static device scratch (no allocation allowed) ----
__device__ __half g_xe[(size_t)MAXN * DN];    // emb in fp16
__device__ __half g_x1[(size_t)MAXN * DN];    // layer-1 out
__device__ __half g_x2[(size_t)MAXN * DN];    // layer-2 out
__device__ int   g_deg[MAXN];
__device__ int   g_rowptr[MAXN];
__device__ int   g_cursor[MAXN];
__device__ int   g_bsum[MAX_SCAN_BLOCKS];
__device__ int2  g_edge[MAXNNZ];              // (col, float_bits(val)) grouped by row

// ---------------------------------------------------------------------------
// CSR build
// ---------------------------------------------------------------------------
__global__ void zero_deg_kernel(int n) {
    int i = blockIdx.x * blockDim.x + threadIdx.x;
    if (i < n) g_deg[i] = 0;
}

__global__ void hist_kernel(const int* __restrict__ rows, int nnz) {
    int e = blockIdx.x * blockDim.x + threadIdx.x;
    if (e < nnz) atomicAdd(&g_deg[rows[e]], 1);
}

__global__ void scan_reduce_kernel(int n) {
    __shared__ int s[SCAN_BLK];
    int base = blockIdx.x * SCAN_CHUNK + threadIdx.x * SCAN_IPT;
    int sum = 0;
#pragma unroll
    for (int i = 0; i < SCAN_IPT; i++) {
        int idx = base + i;
        if (idx < n) sum += g_deg[idx];
    }
    s[threadIdx.x] = sum;
    __syncthreads();
    for (int off = SCAN_BLK / 2; off > 0; off >>= 1) {
        if (threadIdx.x < off) s[threadIdx.x] += s[threadIdx.x + off];
        __syncthreads();
    }
    if (threadIdx.x == 0) g_bsum[blockIdx.x] = s[0];
}

__global__ void scan_top_kernel(int nb) {
    __shared__ int s[64];
    int t = threadIdx.x;
    int own = (t < nb) ? g_bsum[t] : 0;
    s[t] = own;
    __syncthreads();
#pragma unroll
    for (int o = 1; o < 64; o <<= 1) {
        int v = (t >= o) ? s[t - o] : 0;
        __syncthreads();
        s[t] += v;
        __syncthreads();
    }
    if (t < nb) g_bsum[t] = s[t] - own;   // exclusive
}

__global__ void scan_down_kernel(int n) {
    int tid = threadIdx.x;
    int base = blockIdx.x * SCAN_CHUNK + tid * SCAN_IPT;
    int local[SCAN_IPT];
    int sum = 0;
#pragma unroll
    for (int i = 0; i < SCAN_IPT; i++) {
        int idx = base + i;
        int v = (idx < n) ? g_deg[idx] : 0;
        local[i] = sum;
        sum += v;
    }
    int lane = tid & 31, wid = tid >> 5;
    int v = sum;
#pragma unroll
    for (int o = 1; o < 32; o <<= 1) {
        int t = __shfl_up_sync(0xFFFFFFFFu, v, o);
        if (lane >= o) v += t;
    }
    __shared__ int wsum[SCAN_BLK / 32];
    if (lane == 31) wsum[wid] = v;
    __syncthreads();
    if (tid < SCAN_BLK / 32) {
        int w = wsum[tid];
#pragma unroll
        for (int o = 1; o < SCAN_BLK / 32; o <<= 1) {
            int t = __shfl_up_sync(0xFFu, w, o);
            if (tid >= o) w += t;
        }
        wsum[tid] = w;
    }
    __syncthreads();
    int thread_excl = v - sum + (wid ? wsum[wid - 1] : 0);
    int off = thread_excl + g_bsum[blockIdx.x];
#pragma unroll
    for (int i = 0; i < SCAN_IPT; i++) {
        int idx = base + i;
        if (idx < n) {
            int p = off + local[i];
            g_rowptr[idx] = p;
            g_cursor[idx] = p;
        }
    }
}

__global__ void scatter_kernel(const int* __restrict__ rows,
                               const int* __restrict__ cols,
                               const float* __restrict__ vals,
                               int nnz) {
    int e = blockIdx.x * blockDim.x + threadIdx.x;
    if (e >= nnz) return;
    int r = rows[e];
    int pos = atomicAdd(&g_cursor[r], 1);
    g_edge[pos] = make_int2(cols[e], __float_as_int(vals[e]));
}

// ---------------------------------------------------------------------------
// emb (f32) -> f16
// ---------------------------------------------------------------------------
__global__ void f2h_kernel(const float4* __restrict__ src,
                           uint2* __restrict__ dst, int total4) {
    int i = blockIdx.x * blockDim.x + threadIdx.x;
    if (i >= total4) return;
    float4 v = src[i];
    __half2 a = __float22half2_rn(make_float2(v.x, v.y));
    __half2 b = __float22half2_rn(make_float2(v.z, v.w));
    uint2 r;
    r.x = *reinterpret_cast<unsigned int*>(&a);
    r.y = *reinterpret_cast<unsigned int*>(&b);
    dst[i] = r;
}

// ---------------------------------------------------------------------------
// pull SpMM, fp16 operand, fp32 accumulation. Warp per row.
// 4-wide edge unroll -> 4 independent gathers in flight (MLP=4).
// ---------------------------------------------------------------------------
__device__ __forceinline__ float2 h2f_lo(unsigned u) {
    __half2 h = *reinterpret_cast<__half2*>(&u);
    return __half22float2(h);
}

template <bool FUSE>
__global__ void __launch_bounds__(256) spmm_half_kernel(
        const uint2* __restrict__ x,
        uint2* __restrict__ yh,
        const float4* __restrict__ emb,
        const uint2* __restrict__ x1,
        const uint2* __restrict__ x2,
        float4* __restrict__ outf,
        int n) {
    int w = (blockIdx.x * blockDim.x + threadIdx.x) >> 5;
    int lane = threadIdx.x & 31;
    if (w >= n) return;

    int start = g_rowptr[w];
    int end = start + g_deg[w];

    float a0x = 0.f, a0y = 0.f, a0z = 0.f, a0w = 0.f;
    float a1x = 0.f, a1y = 0.f, a1z = 0.f, a1w = 0.f;

    int e = start;
    // 4-wide: issue all 4 gathers before consuming any
    for (; e + 4 <= end; e += 4) {
        int2 e0 = g_edge[e];
        int2 e1 = g_edge[e + 1];
        int2 e2 = g_edge[e + 2];
        int2 e3 = g_edge[e + 3];
        uint2 m0 = __ldg(x + (size_t)e0.x * 32 + lane);
        uint2 m1 = __ldg(x + (size_t)e1.x * 32 + lane);
        uint2 m2 = __ldg(x + (size_t)e2.x * 32 + lane);
        uint2 m3 = __ldg(x + (size_t)e3.x * 32 + lane);
        float v0 = __int_as_float(e0.y);
        float v1 = __int_as_float(e1.y);
        float v2 = __int_as_float(e2.y);
        float v3 = __int_as_float(e3.y);
        {
            float2 fa = h2f_lo(m0.x), fb = h2f_lo(m0.y);
            a0x += v0 * fa.x; a0y += v0 * fa.y; a0z += v0 * fb.x; a0w += v0 * fb.y;
        }
        {
            float2 fa = h2f_lo(m1.x), fb = h2f_lo(m1.y);
            a1x += v1 * fa.x; a1y += v1 * fa.y; a1z += v1 * fb.x; a1w += v1 * fb.y;
        }
        {
            float2 fa = h2f_lo(m2.x), fb = h2f_lo(m2.y);
            a0x += v2 * fa.x; a0y += v2 * fa.y; a0z += v2 * fb.x; a0w += v2 * fb.y;
        }
        {
            float2 fa = h2f_lo(m3.x), fb = h2f_lo(m3.y);
            a1x += v3 * fa.x; a1y += v3 * fa.y; a1z += v3 * fb.x; a1w += v3 * fb.y;
        }
    }
    if (e + 2 <= end) {
        int2 e0 = g_edge[e];
        int2 e1 = g_edge[e + 1];
        uint2 m0 = __ldg(x + (size_t)e0.x * 32 + lane);
        uint2 m1 = __ldg(x + (size_t)e1.x * 32 + lane);
        float v0 = __int_as_float(e0.y);
        float v1 = __int_as_float(e1.y);
        float2 fa = h2f_lo(m0.x), fb = h2f_lo(m0.y);
        a0x += v0 * fa.x; a0y += v0 * fa.y; a0z += v0 * fb.x; a0w += v0 * fb.y;
        float2 fc = h2f_lo(m1.x), fd = h2f_lo(m1.y);
        a1x += v1 * fc.x; a1y += v1 * fc.y; a1z += v1 * fd.x; a1w += v1 * fd.y;
        e += 2;
    }
    if (e < end) {
        int2 e0 = g_edge[e];
        uint2 m0 = __ldg(x + (size_t)e0.x * 32 + lane);
        float v0 = __int_as_float(e0.y);
        float2 fa = h2f_lo(m0.x), fb = h2f_lo(m0.y);
        a0x += v0 * fa.x; a0y += v0 * fa.y; a0z += v0 * fb.x; a0w += v0 * fb.y;
    }

    float rx = a0x + a1x, ry = a0y + a1y, rz = a0z + a1z, rw = a0w + a1w;

    size_t oidx = (size_t)w * 32 + lane;
    if (FUSE) {
        float4 eb = __ldg(emb + oidx);
        uint2 u1 = __ldg(x1 + oidx);
        uint2 u2 = __ldg(x2 + oidx);
        float2 b10 = h2f_lo(u1.x), b11 = h2f_lo(u1.y);
        float2 b20 = h2f_lo(u2.x), b21 = h2f_lo(u2.y);
        float4 o;
        o.x = (rx + eb.x + b10.x + b20.x) * 0.25f;
        o.y = (ry + eb.y + b10.y + b20.y) * 0.25f;
        o.z = (rz + eb.z + b11.x + b21.x) * 0.25f;
        o.w = (rw + eb.w + b11.y + b21.y) * 0.25f;
        outf[oidx] = o;
    } else {
        __half2 ha = __float22half2_rn(make_float2(rx, ry));
        __half2 hb = __float22half2_rn(make_float2(rz, rw));
        uint2 r;
        r.x = *reinterpret_cast<unsigned int*>(&ha);
        r.y = *reinterpret_cast<unsigned int*>(&hb);
        yh[oidx] = r;
    }
}

// ---------------------------------------------------------------------------
extern "C" void kernel_launch(void* const* d_in, const int* in_sizes, int n_in,
                              void* d_out, int out_size) {
    const float* emb  = (const float*)d_in[0];
    const float* vals = (const float*)d_in[1];
    const int*   rows = (const int*)d_in[2];
    const int*   cols = (const int*)d_in[3];
    float* out = (float*)d_out;

    int nnz = in_sizes[1];
    int n   = in_sizes[0] / DN;

    __half* xe; __half* x1; __half* x2;
    cudaGetSymbolAddress((void**)&xe, g_xe);
    cudaGetSymbolAddress((void**)&x1, g_x1);
    cudaGetSymbolAddress((void**)&x2, g_x2);

    const int TB = 256;
    int total4 = in_sizes[0] / 4;
    int nb_scan     = (n + SCAN_CHUNK - 1) / SCAN_CHUNK;
    int deg_blocks  = (n + TB - 1) / TB;
    int edge_blocks = (nnz + TB - 1) / TB;
    int ew_blocks   = (total4 + TB - 1) / TB;
    int spmm_blocks = (n * 32 + TB - 1) / TB;

    // --- CSR build ---
    zero_deg_kernel<<<deg_blocks, TB>>>(n);
    hist_kernel<<<edge_blocks, TB>>>(rows, nnz);
    scan_reduce_kernel<<<nb_scan, SCAN_BLK>>>(n);
    scan_top_kernel<<<1, 64>>>(nb_scan);
    scan_down_kernel<<<nb_scan, SCAN_BLK>>>(n);
    scatter_kernel<<<edge_blocks, TB>>>(rows, cols, vals, nnz);

    // --- emb -> fp16 ---
    f2h_kernel<<<ew_blocks, TB>>>((const float4*)emb, (uint2*)xe, total4);

    // --- 3 layers ---
    spmm_half_kernel<false><<<spmm_blocks, TB>>>(
        (const uint2*)xe, (uint2*)x1, nullptr, nullptr, nullptr, nullptr, n);
    spmm_half_kernel<false><<<spmm_blocks, TB>>>(
        (const uint2*)x1, (uint2*)x2, nullptr, nullptr, nullptr, nullptr, n);
    spmm_half_kernel<true><<<spmm_blocks, TB>>>(
        (const uint2*)x2, nullptr,
        (const float4*)emb, (const uint2*)x1, (const uint2*)x2,
        (float4*)out, n);
}